// round 1
// baseline (speedup 1.0000x reference)
#include <cuda_runtime.h>
#include <math.h>

// Shapes (fixed by problem)
#define B_    256
#define L_    32
#define D_    512
#define H_    512
#define NROWS (B_ * L_)      // 8192 slots
#define NCOMP (5 * H_)       // 2560
#define KCOMP (2 * H_)       // 1024

// ---------------- persistent device state (no runtime alloc allowed) ----------
__device__ float g_h [NROWS * H_];          // element h, by slot
__device__ float g_c [NROWS * H_];          // element c, by slot
__device__ float g_nh[NROWS * H_];          // cached pair compose h (at left slot)
__device__ float g_nc[NROWS * H_];          // cached pair compose c (at left slot)
__device__ float g_v [8192 * NCOMP];        // GEMM scratch (pre-activation gates)
__device__ float g_logit[NROWS];            // cached pair logit (at left slot)
__device__ int   g_idx[B_ * L_];            // per-batch slot index list
__device__ int4  g_tasks[8192];             // (b, left_slot, right_slot, dest_slot)
__device__ int   g_counter[64];             // task counters: [i]=step i, [31]=initial fill

__device__ __forceinline__ float sigmf(float x) { return 1.f / (1.f + expf(-x)); }

// ---------------- init ----------------
__global__ void k_zero() {
    if (threadIdx.x < 64) g_counter[threadIdx.x] = 0;
}

__global__ void k_init(const int* __restrict__ length) {
    int b = blockIdx.x;
    g_idx[b * 32 + threadIdx.x] = threadIdx.x;
    if (threadIdx.x == 0) {
        int vc0 = length[b] - 1;                       // valid pairs at step 0
        int base = atomicAdd(&g_counter[31], vc0);
        for (int k = 0; k < vc0; k++)
            g_tasks[base + k] = make_int4(b, k, k + 1, k);
    }
}

// ---------------- tiled fp32 GEMMs: BM=128, BN=64, BK=16, 256 thr, 8x4/thread --
#define BM 128
#define BN 64
#define BK 16

// word projection: hc = x @ W_word^T + b_word ; h = hc[:,:512], c = hc[:,512:]
__global__ void k_gemm_word(const float* __restrict__ X, const float* __restrict__ W,
                            const float* __restrict__ bias) {
    __shared__ float As[BK][BM + 4];
    __shared__ float Bs[BK][BN + 4];
    int tid = threadIdx.x;
    int mbase = blockIdx.y * BM;
    int nbase = blockIdx.x * BN;
    int tx = tid & 15, ty = tid >> 4;
    float acc[8][4];
#pragma unroll
    for (int i = 0; i < 8; i++)
#pragma unroll
        for (int j = 0; j < 4; j++) acc[i][j] = 0.f;

    int fa0 = tid, fa1 = tid + 256;
    int ar0 = fa0 >> 2, ak0 = (fa0 & 3) * 4;
    int ar1 = fa1 >> 2, ak1 = (fa1 & 3) * 4;
    int br  = tid >> 2, bk  = (tid & 3) * 4;
    const float* Xp0 = X + (size_t)(mbase + ar0) * D_;
    const float* Xp1 = X + (size_t)(mbase + ar1) * D_;
    const float* Wp  = W + (size_t)(nbase + br) * D_;

    for (int kt = 0; kt < D_; kt += BK) {
        float4 a0 = *(const float4*)(Xp0 + kt + ak0);
        float4 a1 = *(const float4*)(Xp1 + kt + ak1);
        float4 bv = *(const float4*)(Wp  + kt + bk);
        As[ak0 + 0][ar0] = a0.x; As[ak0 + 1][ar0] = a0.y;
        As[ak0 + 2][ar0] = a0.z; As[ak0 + 3][ar0] = a0.w;
        As[ak1 + 0][ar1] = a1.x; As[ak1 + 1][ar1] = a1.y;
        As[ak1 + 2][ar1] = a1.z; As[ak1 + 3][ar1] = a1.w;
        Bs[bk + 0][br] = bv.x; Bs[bk + 1][br] = bv.y;
        Bs[bk + 2][br] = bv.z; Bs[bk + 3][br] = bv.w;
        __syncthreads();
#pragma unroll
        for (int kk = 0; kk < BK; kk++) {
            float4 x0 = *(const float4*)&As[kk][ty * 8];
            float4 x1 = *(const float4*)&As[kk][ty * 8 + 4];
            float4 y0 = *(const float4*)&Bs[kk][tx * 4];
            float a[8] = {x0.x, x0.y, x0.z, x0.w, x1.x, x1.y, x1.z, x1.w};
            float b[4] = {y0.x, y0.y, y0.z, y0.w};
#pragma unroll
            for (int im = 0; im < 8; im++)
#pragma unroll
                for (int in = 0; in < 4; in++) acc[im][in] += a[im] * b[in];
        }
        __syncthreads();
    }
#pragma unroll
    for (int im = 0; im < 8; im++) {
        int m = mbase + ty * 8 + im;
#pragma unroll
        for (int in = 0; in < 4; in++) {
            int n = nbase + tx * 4 + in;
            float val = acc[im][in] + bias[n];
            if (n < H_) g_h[m * H_ + n] = val;
            else        g_c[m * H_ + (n - H_)] = val;
        }
    }
}

// compose pre-activations: v = [h_l || h_r] @ W_comp^T + b_comp, rows gathered from tasks
__global__ void k_gemm_comp(const float* __restrict__ W, const float* __restrict__ bias, int ci) {
    int nt = g_counter[ci];
    int mbase = blockIdx.y * BM;
    if (mbase >= nt) return;
    int nbase = blockIdx.x * BN;
    __shared__ float As[BK][BM + 4];
    __shared__ float Bs[BK][BN + 4];
    int tid = threadIdx.x;
    int tx = tid & 15, ty = tid >> 4;
    float acc[8][4];
#pragma unroll
    for (int i = 0; i < 8; i++)
#pragma unroll
        for (int j = 0; j < 4; j++) acc[i][j] = 0.f;

    int fa0 = tid, fa1 = tid + 256;
    int ar0 = fa0 >> 2, ak0 = (fa0 & 3) * 4;
    int ar1 = fa1 >> 2, ak1 = (fa1 & 3) * 4;
    int br  = tid >> 2, bk  = (tid & 3) * 4;

    int m0 = mbase + ar0, m1 = mbase + ar1;
    bool v0 = m0 < nt, v1 = m1 < nt;
    const float *p0l = g_h, *p0r = g_h, *p1l = g_h, *p1r = g_h;
    if (v0) { int4 tk = g_tasks[m0]; p0l = g_h + (tk.x * 32 + tk.y) * H_; p0r = g_h + (tk.x * 32 + tk.z) * H_; }
    if (v1) { int4 tk = g_tasks[m1]; p1l = g_h + (tk.x * 32 + tk.y) * H_; p1r = g_h + (tk.x * 32 + tk.z) * H_; }
    const float* Wp = W + (size_t)(nbase + br) * KCOMP;

    for (int kt = 0; kt < KCOMP; kt += BK) {
        int k0 = kt + ak0, k1 = kt + ak1;
        float4 a0 = make_float4(0.f, 0.f, 0.f, 0.f);
        float4 a1 = make_float4(0.f, 0.f, 0.f, 0.f);
        if (v0) a0 = *(const float4*)((k0 < H_) ? (p0l + k0) : (p0r + k0 - H_));
        if (v1) a1 = *(const float4*)((k1 < H_) ? (p1l + k1) : (p1r + k1 - H_));
        float4 bv = *(const float4*)(Wp + kt + bk);
        As[ak0 + 0][ar0] = a0.x; As[ak0 + 1][ar0] = a0.y;
        As[ak0 + 2][ar0] = a0.z; As[ak0 + 3][ar0] = a0.w;
        As[ak1 + 0][ar1] = a1.x; As[ak1 + 1][ar1] = a1.y;
        As[ak1 + 2][ar1] = a1.z; As[ak1 + 3][ar1] = a1.w;
        Bs[bk + 0][br] = bv.x; Bs[bk + 1][br] = bv.y;
        Bs[bk + 2][br] = bv.z; Bs[bk + 3][br] = bv.w;
        __syncthreads();
#pragma unroll
        for (int kk = 0; kk < BK; kk++) {
            float4 x0 = *(const float4*)&As[kk][ty * 8];
            float4 x1 = *(const float4*)&As[kk][ty * 8 + 4];
            float4 y0 = *(const float4*)&Bs[kk][tx * 4];
            float a[8] = {x0.x, x0.y, x0.z, x0.w, x1.x, x1.y, x1.z, x1.w};
            float b[4] = {y0.x, y0.y, y0.z, y0.w};
#pragma unroll
            for (int im = 0; im < 8; im++)
#pragma unroll
                for (int in = 0; in < 4; in++) acc[im][in] += a[im] * b[in];
        }
        __syncthreads();
    }
#pragma unroll
    for (int im = 0; im < 8; im++) {
        int m = mbase + ty * 8 + im;
        if (m < nt) {
#pragma unroll
            for (int in = 0; in < 4; in++) {
                int n = nbase + tx * 4 + in;
                g_v[(size_t)m * NCOMP + n] = acc[im][in] + bias[n];
            }
        }
    }
}

// compose elementwise: gates -> (nh, nc, logit), cached at dest slot
__global__ void k_ew(const float* __restrict__ q, int ci) {
    int t = blockIdx.x;
    if (t >= g_counter[ci]) return;
    int4 tk = g_tasks[t];
    int b = tk.x, sl = tk.y, sr = tk.z, dst = tk.w;
    const float* v = g_v + (size_t)t * NCOMP;
    int tid = threadIdx.x;
    float accq = 0.f;
    for (int e = tid; e < H_; e += 128) {
        float vi  = v[e];
        float vfl = v[H_ + e];
        float vfr = v[2 * H_ + e];
        float vu  = v[3 * H_ + e];
        float vo  = v[4 * H_ + e];
        float cl = g_c[(b * 32 + sl) * H_ + e];
        float cr = g_c[(b * 32 + sr) * H_ + e];
        float cn = cl * sigmf(vfl + 1.f) + cr * sigmf(vfr + 1.f) + tanhf(vu) * sigmf(vi);
        float hn = sigmf(vo) * tanhf(cn);
        g_nh[(b * 32 + dst) * H_ + e] = hn;
        g_nc[(b * 32 + dst) * H_ + e] = cn;
        accq += q[e] * hn;
    }
    // block reduce (deterministic fixed tree)
    for (int o = 16; o > 0; o >>= 1) accq += __shfl_down_sync(0xffffffffu, accq, o);
    __shared__ float red[4];
    if ((tid & 31) == 0) red[tid >> 5] = accq;
    __syncthreads();
    if (tid == 0) {
        float s = red[0] + red[1] + red[2] + red[3];
        g_logit[b * 32 + dst] = s * 0.04419417382415922f;   // 1/sqrt(512)
    }
}

// per-step: argmax over valid pair logits, commit merge (copy cached compose),
// update slot index list, emit <=2 recompute tasks for step i
__global__ void k_select(const int* __restrict__ length, int step) {
    int b = blockIdx.x;
    __shared__ int s_sl;
    if (threadIdx.x == 0) {
        int len = length[b];
        int vc = len - step - 1;            // valid pair count this step
        int sl = -1;
        if (vc >= 1) {
            int n = 32 - step;              // current element count
            int* ip = g_idx + b * 32;
            float best = -3.0e38f; int jb = 0;
            for (int k = 0; k < vc; k++) {  // first-max tie-break == jnp.argmax
                float lg = g_logit[b * 32 + ip[k]];
                if (lg > best) { best = lg; jb = k; }
            }
            sl = ip[jb];
            if (step < 30) {
                int nt2 = 0; int4 tk[2];
                if (jb >= 1)      tk[nt2++] = make_int4(b, ip[jb - 1], sl, ip[jb - 1]);
                if (jb <= vc - 2) tk[nt2++] = make_int4(b, sl, ip[jb + 2], sl);
                if (nt2) {
                    int base = atomicAdd(&g_counter[step], nt2);
                    for (int t = 0; t < nt2; t++) g_tasks[base + t] = tk[t];
                }
            }
            for (int k = jb + 1; k < n - 1; k++) ip[k] = ip[k + 1];  // delete right elem
        }
        s_sl = sl;
    }
    __syncthreads();
    int sl = s_sl;
    if (sl >= 0) {  // merged value IS the cached compose — just commit it
        float4*       hd = (float4*)      (g_h  + (b * 32 + sl) * H_);
        const float4* hs = (const float4*)(g_nh + (b * 32 + sl) * H_);
        float4*       cd = (float4*)      (g_c  + (b * 32 + sl) * H_);
        const float4* cs = (const float4*)(g_nc + (b * 32 + sl) * H_);
        hd[threadIdx.x] = hs[threadIdx.x];
        cd[threadIdx.x] = cs[threadIdx.x];
    }
}

__global__ void k_final(float* __restrict__ out) {
    int b = blockIdx.x;   // element 0 lives in slot 0 forever
    ((float4*)out)[b * 128 + threadIdx.x] =
        ((const float4*)(g_h + (size_t)b * 32 * H_))[threadIdx.x];
}

// ---------------- launch ----------------
extern "C" void kernel_launch(void* const* d_in, const int* in_sizes, int n_in,
                              void* d_out, int out_size) {
    const float* x      = (const float*)d_in[0];
    const int*   length = (const int*)  d_in[1];
    const float* Ww     = (const float*)d_in[2];
    const float* bw     = (const float*)d_in[3];
    const float* Wc     = (const float*)d_in[4];
    const float* bc     = (const float*)d_in[5];
    const float* q      = (const float*)d_in[6];
    float* out = (float*)d_out;

    k_zero<<<1, 64>>>();
    k_init<<<B_, 32>>>(length);
    k_gemm_word<<<dim3(1024 / BN, NROWS / BM), 256>>>(x, Ww, bw);

    // initial pair-cache fill: up to 31*256 = 7936 rows (counter slot 31)
    k_gemm_comp<<<dim3(NCOMP / BN, (7936 + BM - 1) / BM), 256>>>(Wc, bc, 31);
    k_ew<<<7936, 128>>>(q, 31);

    for (int i = 0; i < 31; i++) {
        k_select<<<B_, 128>>>(length, i);
        if (i < 30) {   // recompute <=2 changed pairs per batch (counter slot i)
            k_gemm_comp<<<dim3(NCOMP / BN, (512 + BM - 1) / BM), 256>>>(Wc, bc, i);
            k_ew<<<512, 128>>>(q, i);
        }
    }
    k_final<<<B_, 128>>>(out);
}

// round 5
// speedup vs baseline: 1.6642x; 1.6642x over previous
#include <cuda_runtime.h>
#include <math.h>

// Shapes (fixed by problem)
#define B_    256
#define L_    32
#define D_    512
#define H_    512
#define NROWS (B_ * L_)      // 8192 slots
#define NCOMP (5 * H_)       // 2560

// ---------------- persistent device state (device-code access ONLY) ------
__device__ float g_h [NROWS * H_];          // element h, by slot
__device__ float g_c [NROWS * H_];          // element c, by slot
__device__ float g_nh[NROWS * H_];          // cached pair-compose h (at left slot)
__device__ float g_nc[NROWS * H_];          // cached pair-compose c (at left slot)
__device__ float g_pl[NROWS * NCOMP];       // cached W_l @ h  per element
__device__ float g_pr[NROWS * NCOMP];       // cached W_r @ h  per element
__device__ float g_logit[NROWS];            // cached pair logit (at left slot)
__device__ int   g_idx[B_ * L_];            // per-batch slot index list
__device__ int   g_et[NROWS + 31 * 256];    // element tasks: slot id (b*32+e)
__device__ int4  g_pt[NROWS + 31 * 512];    // pair tasks (b, sl, sr, dst)
__device__ int   g_ec[34];                  // element-task counters ([32]=initial)
__device__ int   g_pc[34];                  // pair-task counters    ([32]=initial)

__device__ __forceinline__ float sigmf(float x) { return 1.f / (1.f + expf(-x)); }

// ---------------- init ----------------
__global__ void k_zero() {
    if (threadIdx.x < 34) { g_ec[threadIdx.x] = 0; g_pc[threadIdx.x] = 0; }
}

__global__ void k_init(const int* __restrict__ length) {
    int b = blockIdx.x;
    g_idx[b * 32 + threadIdx.x] = threadIdx.x;
    if (threadIdx.x == 0) {
        int len = length[b];
        int be = atomicAdd(&g_ec[32], len);
        for (int e = 0; e < len; e++) g_et[be + e] = b * 32 + e;
        int bp = atomicAdd(&g_pc[32], len - 1);
        for (int k = 0; k < len - 1; k++) g_pt[bp + k] = make_int4(b, k, k + 1, k);
    }
}

// ---------------- gather GEMM over element-task rows, K = 512 ------------
// MODE 0 (word proj): A = X[et], B = Ww (N=1024, ldb=512), +bw, out -> g_h|g_c
// MODE 1 (partials):  A = g_h[et], B = Wc halves (N=5120), out -> g_pl|g_pr
template<int BM, int MODE>
__global__ void k_ggemm(int et_off, int ci,
                        const float* __restrict__ X,
                        const float* __restrict__ W,
                        const float* __restrict__ bias)
{
    constexpr int BN = 64, BK = 16;
    constexpr int TM = BM / 16;                 // rows per thread (8 or 4)
    constexpr int NLA = (BM * BK) / (256 * 4);  // float4 A loads per thread (2 or 1)
    int nt = g_ec[ci];
    int mbase = blockIdx.y * BM;
    if (mbase >= nt) return;
    int nbase = blockIdx.x * BN;
    __shared__ float As[BK][BM + 4];
    __shared__ float Bs[BK][BN + 4];
    int tid = threadIdx.x;
    int tx = tid & 15, ty = tid >> 4;
    float acc[TM][4];
#pragma unroll
    for (int i = 0; i < TM; i++)
#pragma unroll
        for (int j = 0; j < 4; j++) acc[i][j] = 0.f;

    const float* Abase = (MODE == 0) ? X : g_h;
    const float* aptr[NLA];
    int ar[NLA], ak[NLA];
    bool av[NLA];
#pragma unroll
    for (int l = 0; l < NLA; l++) {
        int fa = tid + l * 256;
        ar[l] = fa >> 2; ak[l] = (fa & 3) * 4;
        int m = mbase + ar[l];
        av[l] = (m < nt);
        aptr[l] = av[l] ? (Abase + (size_t)g_et[et_off + m] * 512) : Abase;
    }
    int br = tid >> 2, bk = (tid & 3) * 4;
    int nb = nbase + br;
    const float* wp;
    if (MODE == 0) wp = W + (size_t)nb * 512;                      // Ww row
    else           wp = (nb < NCOMP) ? (W + (size_t)nb * 1024)     // Wc left half
                                     : (W + (size_t)(nb - NCOMP) * 1024 + 512); // right half

    for (int kt = 0; kt < 512; kt += BK) {
#pragma unroll
        for (int l = 0; l < NLA; l++) {
            float4 a = av[l] ? *(const float4*)(aptr[l] + kt + ak[l])
                             : make_float4(0.f, 0.f, 0.f, 0.f);
            As[ak[l] + 0][ar[l]] = a.x; As[ak[l] + 1][ar[l]] = a.y;
            As[ak[l] + 2][ar[l]] = a.z; As[ak[l] + 3][ar[l]] = a.w;
        }
        float4 bv = *(const float4*)(wp + kt + bk);
        Bs[bk + 0][br] = bv.x; Bs[bk + 1][br] = bv.y;
        Bs[bk + 2][br] = bv.z; Bs[bk + 3][br] = bv.w;
        __syncthreads();
#pragma unroll
        for (int kk = 0; kk < BK; kk++) {
            float a[TM], bb[4];
#pragma unroll
            for (int j = 0; j < TM / 4; j++) {
                float4 t = *(const float4*)&As[kk][ty * TM + 4 * j];
                a[4 * j] = t.x; a[4 * j + 1] = t.y; a[4 * j + 2] = t.z; a[4 * j + 3] = t.w;
            }
            {
                float4 t = *(const float4*)&Bs[kk][tx * 4];
                bb[0] = t.x; bb[1] = t.y; bb[2] = t.z; bb[3] = t.w;
            }
#pragma unroll
            for (int im = 0; im < TM; im++)
#pragma unroll
                for (int in = 0; in < 4; in++) acc[im][in] += a[im] * bb[in];
        }
        __syncthreads();
    }
#pragma unroll
    for (int im = 0; im < TM; im++) {
        int m = mbase + ty * TM + im;
        if (m < nt) {
            int s = g_et[et_off + m];
#pragma unroll
            for (int in = 0; in < 4; in++) {
                int nn = nbase + tx * 4 + in;
                if (MODE == 0) {
                    float val = acc[im][in] + bias[nn];
                    if (nn < 512) g_h[(size_t)s * 512 + nn] = val;
                    else          g_c[(size_t)s * 512 + nn - 512] = val;
                } else {
                    float val = acc[im][in];
                    if (nn < NCOMP) g_pl[(size_t)s * NCOMP + nn] = val;
                    else            g_pr[(size_t)s * NCOMP + nn - NCOMP] = val;
                }
            }
        }
    }
}

// ---------------- pair elementwise: gates = pl[sl]+pr[sr]+b -> nh/nc/logit
__global__ void k_ew(int pt_off, int ci,
                     const float* __restrict__ bc, const float* __restrict__ q) {
    int t = blockIdx.x;
    if (t >= g_pc[ci]) return;
    int4 tk = g_pt[pt_off + t];
    int b = tk.x, sl = tk.y, sr = tk.z, dst = tk.w;
    int e = threadIdx.x;   // 128 threads, one float4 (4 elems) each
    const float4* pl  = (const float4*)(g_pl + (size_t)(b * 32 + sl) * NCOMP);
    const float4* pr  = (const float4*)(g_pr + (size_t)(b * 32 + sr) * NCOMP);
    const float4* bc4 = (const float4*)bc;
    const float4* cl4 = (const float4*)(g_c + (size_t)(b * 32 + sl) * H_);
    const float4* cr4 = (const float4*)(g_c + (size_t)(b * 32 + sr) * H_);
    float4* nh4 = (float4*)(g_nh + (size_t)(b * 32 + dst) * H_);
    float4* nc4 = (float4*)(g_nc + (size_t)(b * 32 + dst) * H_);
    const float4* q4 = (const float4*)q;

    float4 vi, vfl, vfr, vu, vo;
#define G(dst_, g_) { float4 a = pl[(g_)*128 + e]; float4 bq = pr[(g_)*128 + e]; float4 c = bc4[(g_)*128 + e]; \
    dst_.x = a.x + bq.x + c.x; dst_.y = a.y + bq.y + c.y; dst_.z = a.z + bq.z + c.z; dst_.w = a.w + bq.w + c.w; }
    G(vi, 0) G(vfl, 1) G(vfr, 2) G(vu, 3) G(vo, 4)
#undef G
    float4 cl = cl4[e], cr = cr4[e];
    float4 cn, hn;
#define C1(m) cn.m = cl.m * sigmf(vfl.m + 1.f) + cr.m * sigmf(vfr.m + 1.f) + tanhf(vu.m) * sigmf(vi.m); \
              hn.m = sigmf(vo.m) * tanhf(cn.m);
    C1(x) C1(y) C1(z) C1(w)
#undef C1
    nh4[e] = hn; nc4[e] = cn;
    float4 qv = q4[e];
    float accq = qv.x * hn.x + qv.y * hn.y + qv.z * hn.z + qv.w * hn.w;
    for (int o = 16; o > 0; o >>= 1) accq += __shfl_down_sync(0xffffffffu, accq, o);
    __shared__ float red[4];
    if ((threadIdx.x & 31) == 0) red[threadIdx.x >> 5] = accq;
    __syncthreads();
    if (threadIdx.x == 0) {
        float s = red[0] + red[1] + red[2] + red[3];
        g_logit[b * 32 + dst] = s * 0.04419417382415922f;   // 1/sqrt(512)
    }
}

// ---------------- per-step argmax, commit merge, emit tasks --------------
__global__ void k_select(const int* __restrict__ length, int step) {
    int b = blockIdx.x;
    __shared__ int s_sl;
    if (threadIdx.x == 0) {
        int len = length[b];
        int vc = len - step - 1;            // valid pair count this step
        int sl = -1;
        if (vc >= 1) {
            int n = 32 - step;              // current element count
            int* ip = g_idx + b * 32;
            float best = -3.0e38f; int jb = 0;
            for (int k = 0; k < vc; k++) {  // first-max tie-break == jnp.argmax
                float lg = g_logit[b * 32 + ip[k]];
                if (lg > best) { best = lg; jb = k; }
            }
            sl = ip[jb];
            if (step < 30) {
                int nt2 = 0; int4 tk[2];
                if (jb >= 1)      tk[nt2++] = make_int4(b, ip[jb - 1], sl, ip[jb - 1]);
                if (jb <= vc - 2) tk[nt2++] = make_int4(b, sl, ip[jb + 2], sl);
                if (nt2) {
                    int base = atomicAdd(&g_pc[step], nt2);
                    for (int t = 0; t < nt2; t++) g_pt[8192 + step * 512 + base + t] = tk[t];
                    int eb = atomicAdd(&g_ec[step], 1);
                    g_et[8192 + step * 256 + eb] = b * 32 + sl;
                }
            }
            for (int k = jb + 1; k < n - 1; k++) ip[k] = ip[k + 1];  // delete right elem
        }
        s_sl = sl;
    }
    __syncthreads();
    int sl = s_sl;
    if (sl >= 0) {  // merged value IS the cached compose — commit it
        float4*       hd = (float4*)      (g_h  + (size_t)(b * 32 + sl) * H_);
        const float4* hs = (const float4*)(g_nh + (size_t)(b * 32 + sl) * H_);
        float4*       cd = (float4*)      (g_c  + (size_t)(b * 32 + sl) * H_);
        const float4* cs = (const float4*)(g_nc + (size_t)(b * 32 + sl) * H_);
        hd[threadIdx.x] = hs[threadIdx.x];
        cd[threadIdx.x] = cs[threadIdx.x];
    }
}

__global__ void k_final(float* __restrict__ out) {
    int b = blockIdx.x;   // element 0 lives in slot 0 forever
    ((float4*)out)[b * 128 + threadIdx.x] =
        ((const float4*)(g_h + (size_t)b * 32 * H_))[threadIdx.x];
}

// ---------------- launch ----------------
extern "C" void kernel_launch(void* const* d_in, const int* in_sizes, int n_in,
                              void* d_out, int out_size) {
    const float* x      = (const float*)d_in[0];
    const int*   length = (const int*)  d_in[1];
    const float* Ww     = (const float*)d_in[2];
    const float* bw     = (const float*)d_in[3];
    const float* Wc     = (const float*)d_in[4];
    const float* bc     = (const float*)d_in[5];
    const float* q      = (const float*)d_in[6];
    float* out = (float*)d_out;

    k_zero<<<1, 64>>>();
    k_init<<<B_, 32>>>(length);

    // word projection (gathered, valid elements only): h|c = x @ Ww^T + bw
    k_ggemm<128, 0><<<dim3(1024 / 64, 64), 256>>>(0, 32, x, Ww, bw);

    // initial partial fill: pl|pr = Wl@h | Wr@h for all valid elements
    k_ggemm<128, 1><<<dim3(NCOMP * 2 / 64, 64), 256>>>(0, 32, (const float*)0, Wc, (const float*)0);

    // initial pair cache (adds + activations + logits)
    k_ew<<<8192, 128>>>(0, 32, bc, q);

    for (int i = 0; i < 31; i++) {
        k_select<<<B_, 128>>>(length, i);
        if (i < 30) {
            // partials for the <=256 merged elements
            k_ggemm<64, 1><<<dim3(NCOMP * 2 / 64, 4), 256>>>(8192 + i * 256, i,
                                                             (const float*)0, Wc, (const float*)0);
            // recompute <=2 changed pairs per batch
            k_ew<<<512, 128>>>(8192 + i * 512, i, bc, q);
        }
    }
    k_final<<<B_, 128>>>(out);
}